// round 15
// baseline (speedup 1.0000x reference)
#include <cuda_runtime.h>

#define BSZ 16
#define SR 16
#define IMW 2048
#define IMH 2048
#define NBX (IMW/BSZ)   // 128
#define NBY (IMH/BSZ)   // 128

#define BPC 4                   // image blocks per CTA (horizontal)
#define WINW (BPC*BSZ + 2*SR)   // 96
#define WINH (BSZ + 2*SR)       // 48
#define RST 98                  // even -> 16B-aligned; 196 words mod 32 = 4 -> optimal 4-phase
#define NTHREADS 352            // 264 j16-threads + 88 j1-threads, zero padding
#define NJ16 264                // 4 blocks x 2 groups x 33 dy, NJ=16 each
#define NJ1 132                 // 4 blocks x 33 dy (dx = 32)

typedef unsigned long long ull;

__device__ __forceinline__ ull f2x_sub(ull a, ull b) {
    ull d; asm("sub.rn.f32x2 %0, %1, %2;" : "=l"(d) : "l"(a), "l"(b)); return d;
}
__device__ __forceinline__ ull f2x_add(ull a, ull b) {
    ull d; asm("add.rn.f32x2 %0, %1, %2;" : "=l"(d) : "l"(a), "l"(b)); return d;
}
__device__ __forceinline__ ull f2x_abs(ull a) {
    return a & 0x7FFFFFFF7FFFFFFFULL;
}
__device__ __forceinline__ ull umin64(ull a, ull b) { return b < a ? b : a; }

__device__ __forceinline__ ull sad_pack(ull acc, int key) {
    float lo = __uint_as_float((unsigned)(acc & 0xFFFFFFFFu));
    float hi = __uint_as_float((unsigned)(acc >> 32));
    float s = lo + hi;
    return ((ull)__float_as_uint(s) << 32) | (ull)(unsigned)key;
}

// one j1 item (dx = 32) for (b, dyi)
__device__ __forceinline__ ull j1_item(const ull* s_cur, const ull* s_ref, int b, int dyi) {
    const int colbase = b * BSZ + 32;   // even
    ull acc = 0ULL;
    #pragma unroll 1
    for (int rp = 0; rp < 8; ++rp) {
        const int prow = rp * 2 + dyi;
        const ulonglong2* cp = reinterpret_cast<const ulonglong2*>(&s_cur[b * 128 + rp * 16]);
        const ulonglong2* rr = reinterpret_cast<const ulonglong2*>(&s_ref[prow * RST + colbase]);
        #pragma unroll
        for (int k = 0; k < 8; k++) {
            ulonglong2 cw = cp[k];
            ulonglong2 rw = rr[k];
            acc = f2x_add(acc, f2x_abs(f2x_sub(cw.x, rw.x)));
            acc = f2x_add(acc, f2x_abs(f2x_sub(cw.y, rw.y)));
        }
    }
    return sad_pack(acc, dyi * 33 + 32);
}

__global__ __launch_bounds__(NTHREADS, 3)   // 3 CTAs/SM, reg cap 60
void me_sad_kernel(const float* __restrict__ cur,
                   const float* __restrict__ refF,
                   float* __restrict__ out)
{
    __shared__ __align__(16) ull s_ref[47 * RST];          // 36.0 KB row-pair window
    __shared__ __align__(16) ull s_cur[BPC * 8 * 16];      // 4 KB
    __shared__ ull s_red[NJ16 + NJ1];                      // 3.1 KB per-item results

    const int t  = threadIdx.x;
    const int cx = blockIdx.x;          // 0..31
    const int by = blockIdx.y;          // 0..127
    const int gx0 = cx * (BPC * BSZ) - SR;
    const int gy0 = by * BSZ - SR;

    // ---- fill ref window (96x48): value feeds .lo of pair-row p and .hi of pair-row p-1
    float* fref = reinterpret_cast<float*>(s_ref);
    for (int i = t; i < WINW * WINH; i += NTHREADS) {
        int pr = i / WINW, pc = i - pr * WINW;
        int gy = gy0 + pr, gx = gx0 + pc;
        float v = 0.0f;
        if ((unsigned)gy < (unsigned)IMH && (unsigned)gx < (unsigned)IMW)
            v = refF[gy * IMW + gx];
        if (pr < WINH - 1) fref[(pr * RST + pc) * 2]           = v;
        if (pr >= 1)       fref[((pr - 1) * RST + pc) * 2 + 1] = v;
    }
    // ---- fill current blocks (4 x 16x16) as row-pairs
    float* fcur = reinterpret_cast<float*>(s_cur);
    for (int i = t; i < BPC * 256; i += NTHREADS) {
        int b = i >> 8;
        int r = (i >> 4) & 15, c = i & 15;
        float v = cur[(by * BSZ + r) * IMW + (cx * BPC + b) * BSZ + c];
        fcur[(b * 128 + (r >> 1) * 16 + c) * 2 + (r & 1)] = v;
    }
    __syncthreads();

    if (t < NJ16) {
        // ---- j16 item: t = b*66 + g*33 + dyi ; dx = 16g + j, j in [0,16)
        const int b   = t / 66;
        const int v0  = t - b * 66;
        const int g   = v0 / 33;
        const int dyi = v0 - g * 33;
        const int colbase = b * BSZ + 16 * g;   // even -> 16B-aligned

        ull acc[16];
        #pragma unroll
        for (int j = 0; j < 16; j++) acc[j] = 0ULL;

        #pragma unroll 1
        for (int rp = 0; rp < 8; ++rp) {
            ull c2[16];
            const ulonglong2* cp = reinterpret_cast<const ulonglong2*>(&s_cur[b * 128 + rp * 16]);
            #pragma unroll
            for (int k = 0; k < 8; k++) { ulonglong2 w = cp[k]; c2[2*k] = w.x; c2[2*k+1] = w.y; }

            const int prow = rp * 2 + dyi;
            ull r2[32];   // need 31 (c+j <= 30), load 32 aligned
            const ulonglong2* rr = reinterpret_cast<const ulonglong2*>(&s_ref[prow * RST + colbase]);
            #pragma unroll
            for (int k = 0; k < 16; k++) { ulonglong2 w = rr[k]; r2[2*k] = w.x; r2[2*k+1] = w.y; }

            #pragma unroll
            for (int j = 0; j < 16; j++) {
                ull a = acc[j];
                #pragma unroll
                for (int c = 0; c < 16; c++)
                    a = f2x_add(a, f2x_abs(f2x_sub(c2[c], r2[c + j])));
                acc[j] = a;
            }
        }
        ull p = 0xFFFFFFFFFFFFFFFFULL;
        #pragma unroll
        for (int j = 0; j < 16; j++)
            p = umin64(p, sad_pack(acc[j], dyi * 33 + 16 * g + j));
        s_red[t] = p;
    } else {
        // ---- j1 threads (88): k covers item k and (k<44) item k+88
        const int k = t - NJ16;
        {
            const int b = k / 33, dyi = k - b * 33;
            s_red[NJ16 + k] = j1_item(s_cur, s_ref, b, dyi);
        }
        if (k < NJ1 - 88) {
            const int k2 = k + 88;
            const int b = k2 / 33, dyi = k2 - b * 33;
            s_red[NJ16 + k2] = j1_item(s_cur, s_ref, b, dyi);
        }
    }
    __syncthreads();

    // ---- per-image-block reduction: warp rb (rb<4) reduces its block's 99 items
    if (t < 128) {
        const int rb = t >> 5;
        const int l  = t & 31;
        const int base = rb * 66;                  // j16 items
        ull best = s_red[base + l];
        best = umin64(best, s_red[base + l + 32]);
        if (l < 2) best = umin64(best, s_red[base + l + 64]);
        const int base2 = NJ16 + rb * 33;          // j1 items
        best = umin64(best, s_red[base2 + l]);
        if (l == 0) best = umin64(best, s_red[base2 + 32]);
        #pragma unroll
        for (int o = 16; o > 0; o >>= 1) {
            ull q = __shfl_xor_sync(0xFFFFFFFFu, best, o);
            best = umin64(best, q);
        }
        if (l == 0) {
            unsigned key = (unsigned)(best & 0xFFFFFFFFu);
            int dyi_b = key / 33;
            int dxi_b = key - dyi_b * 33;
            int bg = by * NBX + cx * BPC + rb;
            out[bg]                 = (float)(dxi_b - SR);
            out[NBX * NBY + bg]     = (float)(dyi_b - SR);
            out[2 * NBX * NBY + bg] = __uint_as_float((unsigned)(best >> 32));
        }
    }
}

extern "C" void kernel_launch(void* const* d_in, const int* in_sizes, int n_in,
                              void* d_out, int out_size)
{
    const float* c  = (const float*)d_in[0];
    const float* r  = (const float*)d_in[1];
    float* out = (float*)d_out;
    dim3 grid(NBX / BPC, NBY);
    me_sad_kernel<<<grid, NTHREADS>>>(c, r, out);
}

// round 16
// speedup vs baseline: 1.3819x; 1.3819x over previous
#include <cuda_runtime.h>

#define BSZ 16
#define SR 16
#define IMW 2048
#define IMH 2048
#define NBX (IMW/BSZ)   // 128
#define NBY (IMH/BSZ)   // 128

#define BPC 2                   // image blocks per CTA (horizontal)
#define WINW (BPC*BSZ + 2*SR)   // 64
#define WINH (BSZ + 2*SR)       // 48
#define RST 66                  // ref row stride in pairs: 528 B -> conflict-free
#define NTHREADS 352            // warps 0-7: j8 (256 items); warps 8-10: j1 (130 items)
#define NJ8 256                 // 2 blocks x 4 groups x 32 dy (dy 0..31)
#define NJ1 130                 // 66 (dy=32, dx 0..32) + 64 (dx=32, dy 0..31)
#define J1T 96                  // j1 threads

typedef unsigned long long ull;

__device__ __forceinline__ ull f2x_sub(ull a, ull b) {
    ull d; asm("sub.rn.f32x2 %0, %1, %2;" : "=l"(d) : "l"(a), "l"(b)); return d;
}
__device__ __forceinline__ ull f2x_add(ull a, ull b) {
    ull d; asm("add.rn.f32x2 %0, %1, %2;" : "=l"(d) : "l"(a), "l"(b)); return d;
}
__device__ __forceinline__ ull f2x_abs(ull a) {
    return a & 0x7FFFFFFF7FFFFFFFULL;
}
__device__ __forceinline__ ull umin64(ull a, ull b) { return b < a ? b : a; }

__device__ __forceinline__ ull sad_pack(ull acc, int key) {
    float lo = __uint_as_float((unsigned)(acc & 0xFFFFFFFFu));
    float hi = __uint_as_float((unsigned)(acc >> 32));
    float s = lo + hi;
    return ((ull)__float_as_uint(s) << 32) | (ull)(unsigned)key;
}

// generic single-offset item (any dxi, incl. odd): scalar LDS.64 loads
__device__ __forceinline__ ull j1_item(const ull* s_cur, const ull* s_ref,
                                       int b, int dyi, int dxi) {
    const int colbase = b * BSZ + dxi;
    ull acc = 0ULL;
    #pragma unroll 1
    for (int rp = 0; rp < 8; ++rp) {
        const int prow = rp * 2 + dyi;
        const ull* cp = &s_cur[b * 128 + rp * 16];
        const ull* rr = &s_ref[prow * RST + colbase];
        #pragma unroll
        for (int k = 0; k < 16; k++)
            acc = f2x_add(acc, f2x_abs(f2x_sub(cp[k], rr[k])));
    }
    return sad_pack(acc, dyi * 33 + dxi);
}

__global__ __launch_bounds__(NTHREADS, 3)
void me_sad_kernel(const float* __restrict__ cur,
                   const float* __restrict__ refF,
                   float* __restrict__ out)
{
    __shared__ __align__(16) ull s_ref[47 * RST];          // 24.8 KB row-pair window
    __shared__ __align__(16) ull s_cur[BPC * 8 * 16];      // 2 KB
    __shared__ ull s_red[NJ8 + NJ1];                       // 3.1 KB

    const int t  = threadIdx.x;
    const int cx = blockIdx.x;          // 0..63
    const int by = blockIdx.y;          // 0..127
    const int gx0 = cx * (BPC * BSZ) - SR;
    const int gy0 = by * BSZ - SR;

    // ---- fill ref window (64x48): value feeds .lo of pair-row p and .hi of pair-row p-1
    float* fref = reinterpret_cast<float*>(s_ref);
    for (int i = t; i < WINW * WINH; i += NTHREADS) {
        int pr = i / WINW, pc = i - pr * WINW;
        int gy = gy0 + pr, gx = gx0 + pc;
        float v = 0.0f;
        if ((unsigned)gy < (unsigned)IMH && (unsigned)gx < (unsigned)IMW)
            v = refF[gy * IMW + gx];
        if (pr < WINH - 1) fref[(pr * RST + pc) * 2]           = v;
        if (pr >= 1)       fref[((pr - 1) * RST + pc) * 2 + 1] = v;
    }
    // ---- fill current blocks (2 x 16x16) as row-pairs
    float* fcur = reinterpret_cast<float*>(s_cur);
    for (int i = t; i < BPC * 256; i += NTHREADS) {
        int b = i >> 8;
        int r = (i >> 4) & 15, c = i & 15;
        float v = cur[(by * BSZ + r) * IMW + (cx * BPC + b) * BSZ + c];
        fcur[(b * 128 + (r >> 1) * 16 + c) * 2 + (r & 1)] = v;
    }
    __syncthreads();

    if (t < NJ8) {
        // ---- j8 item (warps 0-7, uniform): t = b*128 + g*32 + dyi ; dy 0..31, dx = 8g+j
        const int b   = t >> 7;
        const int v0  = t & 127;
        const int g   = v0 >> 5;
        const int dyi = v0 & 31;
        const int colbase = b * BSZ + 8 * g;   // even -> 16B-aligned

        ull acc[8];
        #pragma unroll
        for (int j = 0; j < 8; j++) acc[j] = 0ULL;

        #pragma unroll 2
        for (int rp = 0; rp < 8; ++rp) {
            ull c2[16];
            const ulonglong2* cp = reinterpret_cast<const ulonglong2*>(&s_cur[b * 128 + rp * 16]);
            #pragma unroll
            for (int k = 0; k < 8; k++) { ulonglong2 w = cp[k]; c2[2*k] = w.x; c2[2*k+1] = w.y; }

            const int prow = rp * 2 + dyi;
            ull r2[24];   // need 23, load 24 aligned
            const ulonglong2* rr = reinterpret_cast<const ulonglong2*>(&s_ref[prow * RST + colbase]);
            #pragma unroll
            for (int k = 0; k < 12; k++) { ulonglong2 w = rr[k]; r2[2*k] = w.x; r2[2*k+1] = w.y; }

            #pragma unroll
            for (int j = 0; j < 8; j++) {
                ull a = acc[j];
                #pragma unroll
                for (int c = 0; c < 16; c++)
                    a = f2x_add(a, f2x_abs(f2x_sub(c2[c], r2[c + j])));
                acc[j] = a;
            }
        }
        ull p = 0xFFFFFFFFFFFFFFFFULL;
        #pragma unroll
        for (int j = 0; j < 8; j++)
            p = umin64(p, sad_pack(acc[j], dyi * 33 + 8 * g + j));
        s_red[t] = p;
    } else {
        // ---- j1 warps (8-10, uniform): idx covers item idx and idx+J1T
        const int idx = t - NJ8;               // 0..95
        #pragma unroll 1
        for (int k = idx; k < NJ1; k += J1T) {
            int b, dyi, dxi;
            if (k < 66) { b = k / 33; dxi = k - b * 33; dyi = 32; }          // dy=32 row
            else { int k2 = k - 66; b = k2 >> 5; dyi = k2 & 31; dxi = 32; }  // dx=32 col
            s_red[NJ8 + k] = j1_item(s_cur, s_ref, b, dyi, dxi);
        }
    }
    __syncthreads();

    // ---- per-image-block reduction: warp rb (rb<2) reduces its block's 161 entries
    if (t < 64) {
        const int rb = t >> 5;
        const int l  = t & 31;
        const int base = rb * 128;                 // j8 items
        ull best = s_red[base + l];
        best = umin64(best, s_red[base + l + 32]);
        best = umin64(best, s_red[base + l + 64]);
        best = umin64(best, s_red[base + l + 96]);
        const int b1 = NJ8 + rb * 33;              // dy=32 row (33 items)
        best = umin64(best, s_red[b1 + l]);
        if (l == 0) best = umin64(best, s_red[b1 + 32]);
        const int b2 = NJ8 + 66 + rb * 32;         // dx=32 col (32 items)
        best = umin64(best, s_red[b2 + l]);
        #pragma unroll
        for (int o = 16; o > 0; o >>= 1) {
            ull q = __shfl_xor_sync(0xFFFFFFFFu, best, o);
            best = umin64(best, q);
        }
        if (l == 0) {
            unsigned key = (unsigned)(best & 0xFFFFFFFFu);
            int dyi_b = key / 33;
            int dxi_b = key - dyi_b * 33;
            int bg = by * NBX + cx * BPC + rb;
            out[bg]                 = (float)(dxi_b - SR);
            out[NBX * NBY + bg]     = (float)(dyi_b - SR);
            out[2 * NBX * NBY + bg] = __uint_as_float((unsigned)(best >> 32));
        }
    }
}

extern "C" void kernel_launch(void* const* d_in, const int* in_sizes, int n_in,
                              void* d_out, int out_size)
{
    const float* c  = (const float*)d_in[0];
    const float* r  = (const float*)d_in[1];
    float* out = (float*)d_out;
    dim3 grid(NBX / BPC, NBY);
    me_sad_kernel<<<grid, NTHREADS>>>(c, r, out);
}

// round 17
// speedup vs baseline: 1.3852x; 1.0024x over previous
#include <cuda_runtime.h>

#define BSZ 16
#define SR 16
#define IMW 2048
#define IMH 2048
#define NBX (IMW/BSZ)   // 128
#define NBY (IMH/BSZ)   // 128

#define BPC 2                   // image blocks per CTA (horizontal)
#define WINW (BPC*BSZ + 2*SR)   // 64
#define WINH (BSZ + 2*SR)       // 48
#define RST 66                  // ref row stride in pairs: 528 B -> conflict-free
#define NTHREADS 352            // warps 0-7: j8 (256 items); warps 8-10: j1 (130 items)
#define NJ8 256                 // 2 blocks x 4 groups x 32 dy (dy 0..31)
#define NJ1 130                 // 66 (dy=32, dx 0..32) + 64 (dx=32, dy 0..31)
#define J1T 96                  // j1 threads

typedef unsigned long long ull;

__device__ __forceinline__ ull f2x_sub(ull a, ull b) {
    ull d; asm("sub.rn.f32x2 %0, %1, %2;" : "=l"(d) : "l"(a), "l"(b)); return d;
}
__device__ __forceinline__ ull f2x_add(ull a, ull b) {
    ull d; asm("add.rn.f32x2 %0, %1, %2;" : "=l"(d) : "l"(a), "l"(b)); return d;
}
__device__ __forceinline__ ull f2x_abs(ull a) {
    return a & 0x7FFFFFFF7FFFFFFFULL;
}
__device__ __forceinline__ ull umin64(ull a, ull b) { return b < a ? b : a; }

__device__ __forceinline__ ull sad_pack(ull acc, int key) {
    float lo = __uint_as_float((unsigned)(acc & 0xFFFFFFFFu));
    float hi = __uint_as_float((unsigned)(acc >> 32));
    float s = lo + hi;
    return ((ull)__float_as_uint(s) << 32) | (ull)(unsigned)key;
}

// data-dependent zero: acc's low word is a non-negative float => sign bit 0.
// Compiler cannot fold it, so loads whose address adds 'dep' must wait for acc.
__device__ __forceinline__ int dep_zero(ull acc) {
    return (int)((unsigned)acc >> 31);
}

// generic single-offset item (any dxi, incl. odd): scalar LDS.64 loads
__device__ __forceinline__ ull j1_item(const ull* s_cur, const ull* s_ref,
                                       int b, int dyi, int dxi) {
    const int colbase = b * BSZ + dxi;
    ull acc = 0ULL;
    #pragma unroll 1
    for (int rp = 0; rp < 8; ++rp) {
        const int prow = rp * 2 + dyi;
        const ull* cp = &s_cur[b * 128 + rp * 16];
        const ull* rr = &s_ref[prow * RST + colbase];
        #pragma unroll
        for (int k = 0; k < 16; k++)
            acc = f2x_add(acc, f2x_abs(f2x_sub(cp[k], rr[k])));
    }
    return sad_pack(acc, dyi * 33 + dxi);
}

__global__ __launch_bounds__(NTHREADS, 3)
void me_sad_kernel(const float* __restrict__ cur,
                   const float* __restrict__ refF,
                   float* __restrict__ out)
{
    __shared__ __align__(16) ull s_ref[47 * RST];          // 24.8 KB row-pair window
    __shared__ __align__(16) ull s_cur[BPC * 8 * 16];      // 2 KB
    __shared__ ull s_red[NJ8 + NJ1];                       // 3.1 KB

    const int t  = threadIdx.x;
    const int cx = blockIdx.x;          // 0..63
    const int by = blockIdx.y;          // 0..127
    const int gx0 = cx * (BPC * BSZ) - SR;
    const int gy0 = by * BSZ - SR;

    // ---- fill ref window (64x48): value feeds .lo of pair-row p and .hi of pair-row p-1
    float* fref = reinterpret_cast<float*>(s_ref);
    for (int i = t; i < WINW * WINH; i += NTHREADS) {
        int pr = i / WINW, pc = i - pr * WINW;
        int gy = gy0 + pr, gx = gx0 + pc;
        float v = 0.0f;
        if ((unsigned)gy < (unsigned)IMH && (unsigned)gx < (unsigned)IMW)
            v = refF[gy * IMW + gx];
        if (pr < WINH - 1) fref[(pr * RST + pc) * 2]           = v;
        if (pr >= 1)       fref[((pr - 1) * RST + pc) * 2 + 1] = v;
    }
    // ---- fill current blocks (2 x 16x16) as row-pairs
    float* fcur = reinterpret_cast<float*>(s_cur);
    for (int i = t; i < BPC * 256; i += NTHREADS) {
        int b = i >> 8;
        int r = (i >> 4) & 15, c = i & 15;
        float v = cur[(by * BSZ + r) * IMW + (cx * BPC + b) * BSZ + c];
        fcur[(b * 128 + (r >> 1) * 16 + c) * 2 + (r & 1)] = v;
    }
    __syncthreads();

    if (t < NJ8) {
        // ---- j8 item (warps 0-7, uniform): t = b*128 + g*32 + dyi ; dy 0..31, dx = 8g+j
        const int b   = t >> 7;
        const int v0  = t & 127;
        const int g   = v0 >> 5;
        const int dyi = v0 & 31;
        const int colbase = b * BSZ + 8 * g;   // even -> 16B-aligned

        ull acc[8];
        #pragma unroll
        for (int j = 0; j < 8; j++) acc[j] = 0ULL;

        #pragma unroll 2
        for (int rp = 0; rp < 8; ++rp) {
            ull c2[16];
            const ulonglong2* cp = reinterpret_cast<const ulonglong2*>(&s_cur[b * 128 + rp * 16]);
            #pragma unroll
            for (int k = 0; k < 8; k++) { ulonglong2 w = cp[k]; c2[2*k] = w.x; c2[2*k+1] = w.y; }

            const int prow = rp * 2 + dyi;
            ull r2[24];
            const ulonglong2* rr = reinterpret_cast<const ulonglong2*>(&s_ref[prow * RST + colbase]);
            // ---- first half of r2: pairs 0..11 (6 LDS.128)
            #pragma unroll
            for (int k = 0; k < 6; k++) { ulonglong2 w = rr[k]; r2[2*k] = w.x; r2[2*k+1] = w.y; }

            // ---- math chunk 1: c in [0,4)  (needs r2[0..10] only)
            #pragma unroll
            for (int j = 0; j < 8; j++) {
                ull a = acc[j];
                #pragma unroll
                for (int c = 0; c < 4; c++)
                    a = f2x_add(a, f2x_abs(f2x_sub(c2[c], r2[c + j])));
                acc[j] = a;
            }

            // ---- second half of r2, address forced to depend on chunk-1 result
            const int dep = dep_zero(acc[0]);    // always 0, but data-dependent
            const ulonglong2* rr2 = rr + 6 + dep;
            #pragma unroll
            for (int k = 0; k < 6; k++) { ulonglong2 w = rr2[k]; r2[12+2*k] = w.x; r2[13+2*k] = w.y; }

            // ---- math chunk 2: c in [4,16)
            #pragma unroll
            for (int j = 0; j < 8; j++) {
                ull a = acc[j];
                #pragma unroll
                for (int c = 4; c < 16; c++)
                    a = f2x_add(a, f2x_abs(f2x_sub(c2[c], r2[c + j])));
                acc[j] = a;
            }
        }
        ull p = 0xFFFFFFFFFFFFFFFFULL;
        #pragma unroll
        for (int j = 0; j < 8; j++)
            p = umin64(p, sad_pack(acc[j], dyi * 33 + 8 * g + j));
        s_red[t] = p;
    } else {
        // ---- j1 warps (8-10, uniform): idx covers item idx and idx+J1T
        const int idx = t - NJ8;               // 0..95
        #pragma unroll 1
        for (int k = idx; k < NJ1; k += J1T) {
            int b, dyi, dxi;
            if (k < 66) { b = k / 33; dxi = k - b * 33; dyi = 32; }          // dy=32 row
            else { int k2 = k - 66; b = k2 >> 5; dyi = k2 & 31; dxi = 32; }  // dx=32 col
            s_red[NJ8 + k] = j1_item(s_cur, s_ref, b, dyi, dxi);
        }
    }
    __syncthreads();

    // ---- per-image-block reduction: warp rb (rb<2) reduces its block's 161 entries
    if (t < 64) {
        const int rb = t >> 5;
        const int l  = t & 31;
        const int base = rb * 128;                 // j8 items
        ull best = s_red[base + l];
        best = umin64(best, s_red[base + l + 32]);
        best = umin64(best, s_red[base + l + 64]);
        best = umin64(best, s_red[base + l + 96]);
        const int b1 = NJ8 + rb * 33;              // dy=32 row (33 items)
        best = umin64(best, s_red[b1 + l]);
        if (l == 0) best = umin64(best, s_red[b1 + 32]);
        const int b2 = NJ8 + 66 + rb * 32;         // dx=32 col (32 items)
        best = umin64(best, s_red[b2 + l]);
        #pragma unroll
        for (int o = 16; o > 0; o >>= 1) {
            ull q = __shfl_xor_sync(0xFFFFFFFFu, best, o);
            best = umin64(best, q);
        }
        if (l == 0) {
            unsigned key = (unsigned)(best & 0xFFFFFFFFu);
            int dyi_b = key / 33;
            int dxi_b = key - dyi_b * 33;
            int bg = by * NBX + cx * BPC + rb;
            out[bg]                 = (float)(dxi_b - SR);
            out[NBX * NBY + bg]     = (float)(dyi_b - SR);
            out[2 * NBX * NBY + bg] = __uint_as_float((unsigned)(best >> 32));
        }
    }
}

extern "C" void kernel_launch(void* const* d_in, const int* in_sizes, int n_in,
                              void* d_out, int out_size)
{
    const float* c  = (const float*)d_in[0];
    const float* r  = (const float*)d_in[1];
    float* out = (float*)d_out;
    dim3 grid(NBX / BPC, NBY);
    me_sad_kernel<<<grid, NTHREADS>>>(c, r, out);
}